// round 1
// baseline (speedup 1.0000x reference)
#include <cuda_runtime.h>
#include <cstdint>
#include <cstddef>

#define BB 128
#define NN 400
#define FF 128
#define KNN 5
#define BN (BB * NN)   // 51200

// ---------------- device scratch (static allocation is allowed) ----------------
__device__ float g_sq[BN];
__device__ unsigned char g_A[(size_t)BN * NN];   // dense symmetric adjacency, 20.5 MB
__device__ float g_m[(size_t)BN * FF];           // aggregated features
__device__ float g_h[(size_t)BN * FF];           // layer-1 output

// ---------------- squared norms ----------------
__global__ void sq_kernel(const float* __restrict__ x) {
    int row = blockIdx.x * 4 + (threadIdx.x >> 5);
    int lane = threadIdx.x & 31;
    float4 v = *(const float4*)(x + (size_t)row * FF + lane * 4);
    float s = v.x * v.x + v.y * v.y + v.z * v.z + v.w * v.w;
#pragma unroll
    for (int o = 16; o; o >>= 1) s += __shfl_xor_sync(0xffffffffu, s, o);
    if (lane == 0) g_sq[row] = s;
}

// ---------------- fused distance + top-5 + adjacency scatter ----------------
// smem: xiT 128x32, xjT 128x128 (k-major, 16B-chunk XOR swizzle), tile scores 32x132,
// sq 416, running top-5 (val+idx) 32x5 each.
#define KNN_SMEM ((128 * 32 + 128 * 128 + 32 * 132 + 416 + 32 * 5 + 32 * 5) * 4)

__global__ void knn_kernel(const float* __restrict__ x) {
    extern __shared__ float sm[];
    float* s_xiT = sm;                   // 128 x 32
    float* s_xjT = s_xiT + 128 * 32;     // 128 x 128
    float* s_sc  = s_xjT + 128 * 128;    // 32 x 132
    float* s_sq  = s_sc + 32 * 132;      // 416
    float* s_bv  = s_sq + 416;           // 32 x 5
    int*   s_bi  = (int*)(s_bv + 32 * 5);// 32 x 5

    const int b  = blockIdx.y;
    const int i0 = blockIdx.x * 32;
    const int ni = min(32, NN - i0);
    const int t  = threadIdx.x;
    const float INF = __int_as_float(0x7f800000);
    const float* xb = x + (size_t)b * NN * FF;

    for (int j = t; j < NN; j += 256) s_sq[j] = g_sq[b * NN + j];
    if (t < 32 * KNN) { s_bv[t] = INF; s_bi[t] = 0x7fffffff; }

    // load xi tile, transpose to k-major with swizzle
    {
        int rb = t >> 5, kc = t & 31;
        float vv[4][4];
#pragma unroll
        for (int r = 0; r < 4; r++) {
            int ir = rb * 4 + r;
            float4 v = (ir < ni) ? *(const float4*)(xb + (size_t)(i0 + ir) * FF + kc * 4)
                                 : make_float4(0.f, 0.f, 0.f, 0.f);
            vv[r][0] = v.x; vv[r][1] = v.y; vv[r][2] = v.z; vv[r][3] = v.w;
        }
#pragma unroll
        for (int c = 0; c < 4; c++) {
            int k = kc * 4 + c;
            *(float4*)&s_xiT[k * 32 + (((rb ^ kc) & 7) << 2)] =
                make_float4(vv[0][c], vv[1][c], vv[2][c], vv[3][c]);
        }
    }

    const int tx = t & 31, ty = t >> 5;
    const int w = t >> 5, lane = t & 31;

    for (int j0 = 0; j0 < NN; j0 += 128) {
        __syncthreads();
        // load xj tile, transpose k-major + swizzle
        for (int idx = t; idx < 1024; idx += 256) {
            int ob = idx >> 5, kc = idx & 31;
            float vv[4][4];
#pragma unroll
            for (int r = 0; r < 4; r++) {
                int jr = j0 + ob * 4 + r;
                float4 v = (jr < NN) ? *(const float4*)(xb + (size_t)jr * FF + kc * 4)
                                     : make_float4(0.f, 0.f, 0.f, 0.f);
                vv[r][0] = v.x; vv[r][1] = v.y; vv[r][2] = v.z; vv[r][3] = v.w;
            }
#pragma unroll
            for (int c = 0; c < 4; c++) {
                int k = kc * 4 + c;
                *(float4*)&s_xjT[k * 128 + (((ob ^ kc) & 31) << 2)] =
                    make_float4(vv[0][c], vv[1][c], vv[2][c], vv[3][c]);
            }
        }
        __syncthreads();

        float acc[4][4] = {};
#pragma unroll 4
        for (int k = 0; k < 128; k++) {
            int sw = k >> 2;
            float4 a  = *(const float4*)&s_xiT[k * 32  + (((ty ^ sw) & 7)  << 2)];
            float4 bj = *(const float4*)&s_xjT[k * 128 + (((tx ^ sw) & 31) << 2)];
            acc[0][0] += a.x * bj.x; acc[0][1] += a.x * bj.y; acc[0][2] += a.x * bj.z; acc[0][3] += a.x * bj.w;
            acc[1][0] += a.y * bj.x; acc[1][1] += a.y * bj.y; acc[1][2] += a.y * bj.z; acc[1][3] += a.y * bj.w;
            acc[2][0] += a.z * bj.x; acc[2][1] += a.z * bj.y; acc[2][2] += a.z * bj.z; acc[2][3] += a.z * bj.w;
            acc[3][0] += a.w * bj.x; acc[3][1] += a.w * bj.y; acc[3][2] += a.w * bj.z; acc[3][3] += a.w * bj.w;
        }
        bool valid = (j0 + tx * 4 + 3) < NN;   // NN%4==0 -> uniform per float4
#pragma unroll
        for (int r = 0; r < 4; r++) {
            int i = ty * 4 + r;
            float4 sc;
            if (valid) {
                int jg = j0 + tx * 4;
                sc = make_float4(s_sq[jg + 0] - 2.f * acc[r][0],
                                 s_sq[jg + 1] - 2.f * acc[r][1],
                                 s_sq[jg + 2] - 2.f * acc[r][2],
                                 s_sq[jg + 3] - 2.f * acc[r][3]);
            } else sc = make_float4(INF, INF, INF, INF);
            *(float4*)&s_sc[i * 132 + tx * 4] = sc;
        }
        __syncthreads();

        // per-row top-5 of this tile, merged into running sorted top-5
        for (int rr = 0; rr < 4; rr++) {
            int i = w * 4 + rr;
            if (i < ni) {
                float* row = &s_sc[i * 132];
                float tv[KNN]; int ti[KNN];
                for (int q = 0; q < KNN; q++) {
                    float bv = INF; int bi = 0x7fffffff;
#pragma unroll
                    for (int ms = 0; ms < 4; ms++) {
                        int c = lane + ms * 32;
                        float v = row[c];
                        int jg = j0 + c;
                        if (v < bv || (v == bv && jg < bi)) { bv = v; bi = jg; }
                    }
#pragma unroll
                    for (int o = 16; o; o >>= 1) {
                        float ov = __shfl_xor_sync(0xffffffffu, bv, o);
                        int   oi = __shfl_xor_sync(0xffffffffu, bi, o);
                        if (ov < bv || (ov == bv && oi < bi)) { bv = ov; bi = oi; }
                    }
                    tv[q] = bv; ti[q] = bi;
                    if (lane == 0) row[bi - j0] = INF;
                    __syncwarp();
                }
                if (lane == 0) {
                    float rv[KNN]; int ri[KNN];
                    float* av = &s_bv[i * KNN]; int* ai = &s_bi[i * KNN];
                    int p = 0, q = 0;
#pragma unroll
                    for (int o = 0; o < KNN; o++) {
                        float va = av[p], vt = tv[q];
                        bool takeA = (va < vt) || (va == vt && ai[p] < ti[q]);
                        if (takeA) { rv[o] = va; ri[o] = ai[p]; p++; }
                        else       { rv[o] = vt; ri[o] = ti[q]; q++; }
                    }
#pragma unroll
                    for (int o = 0; o < KNN; o++) { av[o] = rv[o]; ai[o] = ri[o]; }
                }
            }
            __syncwarp();
        }
    }
    __syncthreads();

    // scatter symmetric adjacency
    for (int rr = 0; rr < 4; rr++) {
        int i = w * 4 + rr;
        if (i < ni && lane == 0) {
            int gi = b * NN + i0 + i;
#pragma unroll
            for (int q = 0; q < KNN; q++) {
                int j = s_bi[i * KNN + q];
                g_A[(size_t)gi * NN + j] = 1;
                g_A[((size_t)(b * NN + j)) * NN + (i0 + i)] = 1;
            }
        }
    }
}

// ---------------- mean aggregation over adjacency (deterministic ballot compaction) ----------------
__global__ void agg_kernel(const float* __restrict__ src, float* __restrict__ dst) {
    __shared__ short s_list[NN];
    __shared__ int s_wc[4];
    int gi = blockIdx.x;
    int b  = gi / NN;
    const unsigned char* Arow = g_A + (size_t)gi * NN;
    int t = threadIdx.x, w = t >> 5, lane = t & 31;
    int jb = w * 100;                 // each warp owns 100 contiguous j
    unsigned m[4]; int cnt = 0;
#pragma unroll
    for (int c = 0; c < 4; c++) {
        int li = c * 32 + lane;
        bool p = (li < 100) && (Arow[jb + li] != 0);
        m[c] = __ballot_sync(0xffffffffu, p);
        cnt += __popc(m[c]);
    }
    if (lane == 0) s_wc[w] = cnt;
    __syncthreads();
    int base = 0;
    for (int ww = 0; ww < w; ww++) base += s_wc[ww];
    int total = s_wc[0] + s_wc[1] + s_wc[2] + s_wc[3];
#pragma unroll
    for (int c = 0; c < 4; c++) {
        int li = c * 32 + lane;
        if (m[c] & (1u << lane)) {
            int pos = base + __popc(m[c] & ((1u << lane) - 1u));
            s_list[pos] = (short)(jb + li);
        }
        base += __popc(m[c]);
    }
    __syncthreads();
    const float* sb = src + (size_t)b * NN * FF;
    float acc = 0.f;
    for (int e = 0; e < total; e++)
        acc += sb[(size_t)s_list[e] * FF + t];      // coalesced 512B row reads
    dst[(size_t)gi * FF + t] = acc / (float)total;
}

// ---------------- fused dual-GEMM: out = act( Xa@Wa^T + Xb@Wb^T + bias ) ----------------
#define GEMM_SMEM ((128 * 32 + 128 * 128) * 4)

template <bool RELU>
__global__ void gemm_kernel(const float* __restrict__ Xa, const float* __restrict__ Wa,
                            const float* __restrict__ Xb, const float* __restrict__ Wb,
                            const float* __restrict__ bias, float* __restrict__ out) {
    extern __shared__ float sm2[];
    float* s_XT = sm2;              // 128 x 32  (k-major, swizzled)
    float* s_WT = sm2 + 128 * 32;   // 128 x 128 (k-major, swizzled)
    const int r0 = blockIdx.x * 32;
    const int t  = threadIdx.x;
    const int tx = t & 31, ty = t >> 5;
    float acc[4][4] = {};
#pragma unroll
    for (int phase = 0; phase < 2; phase++) {
        const float* X = phase ? Xb : Xa;
        const float* W = phase ? Wb : Wa;
        if (phase) __syncthreads();
        {   // X tile: 32 rows x 128 k
            int rb = t >> 5, kc = t & 31;
            float vv[4][4];
#pragma unroll
            for (int r = 0; r < 4; r++) {
                float4 v = *(const float4*)(X + (size_t)(r0 + rb * 4 + r) * FF + kc * 4);
                vv[r][0] = v.x; vv[r][1] = v.y; vv[r][2] = v.z; vv[r][3] = v.w;
            }
#pragma unroll
            for (int c = 0; c < 4; c++)
                *(float4*)&s_XT[(kc * 4 + c) * 32 + (((rb ^ kc) & 7) << 2)] =
                    make_float4(vv[0][c], vv[1][c], vv[2][c], vv[3][c]);
        }
        // W tile: 128 rows x 128 k
        for (int idx = t; idx < 1024; idx += 256) {
            int ob = idx >> 5, kc = idx & 31;
            float vv[4][4];
#pragma unroll
            for (int r = 0; r < 4; r++) {
                float4 v = *(const float4*)(W + (size_t)(ob * 4 + r) * FF + kc * 4);
                vv[r][0] = v.x; vv[r][1] = v.y; vv[r][2] = v.z; vv[r][3] = v.w;
            }
#pragma unroll
            for (int c = 0; c < 4; c++)
                *(float4*)&s_WT[(kc * 4 + c) * 128 + (((ob ^ kc) & 31) << 2)] =
                    make_float4(vv[0][c], vv[1][c], vv[2][c], vv[3][c]);
        }
        __syncthreads();
#pragma unroll 4
        for (int k = 0; k < 128; k++) {
            int sw = k >> 2;
            float4 a  = *(const float4*)&s_XT[k * 32  + (((ty ^ sw) & 7)  << 2)];
            float4 wv = *(const float4*)&s_WT[k * 128 + (((tx ^ sw) & 31) << 2)];
            acc[0][0] += a.x * wv.x; acc[0][1] += a.x * wv.y; acc[0][2] += a.x * wv.z; acc[0][3] += a.x * wv.w;
            acc[1][0] += a.y * wv.x; acc[1][1] += a.y * wv.y; acc[1][2] += a.y * wv.z; acc[1][3] += a.y * wv.w;
            acc[2][0] += a.z * wv.x; acc[2][1] += a.z * wv.y; acc[2][2] += a.z * wv.z; acc[2][3] += a.z * wv.w;
            acc[3][0] += a.w * wv.x; acc[3][1] += a.w * wv.y; acc[3][2] += a.w * wv.z; acc[3][3] += a.w * wv.w;
        }
    }
    float4 bv = *(const float4*)(bias + tx * 4);
    float bb[4] = {bv.x, bv.y, bv.z, bv.w};
#pragma unroll
    for (int r = 0; r < 4; r++) {
        int row = r0 + ty * 4 + r;
        float4 o4;
        float* op = (float*)&o4;
#pragma unroll
        for (int c = 0; c < 4; c++) {
            float v = acc[r][c] + bb[c];
            if (RELU) v = fmaxf(v, 0.f);
            op[c] = v;
        }
        *(float4*)(out + (size_t)row * FF + tx * 4) = o4;
    }
}

// ---------------- launch ----------------
extern "C" void kernel_launch(void* const* d_in, const int* in_sizes, int n_in,
                              void* d_out, int out_size) {
    const float* x   = (const float*)d_in[0];
    const float* W1l = (const float*)d_in[1];
    const float* b1l = (const float*)d_in[2];
    const float* W1r = (const float*)d_in[3];
    const float* W2l = (const float*)d_in[4];
    const float* b2l = (const float*)d_in[5];
    const float* W2r = (const float*)d_in[6];
    float* out = (float*)d_out;

    void* aptr = nullptr;
    cudaGetSymbolAddress(&aptr, g_A);
    float* mp = nullptr; cudaGetSymbolAddress((void**)&mp, g_m);
    float* hp = nullptr; cudaGetSymbolAddress((void**)&hp, g_h);

    cudaFuncSetAttribute(knn_kernel, cudaFuncAttributeMaxDynamicSharedMemorySize, KNN_SMEM);
    cudaFuncSetAttribute(gemm_kernel<true>,  cudaFuncAttributeMaxDynamicSharedMemorySize, GEMM_SMEM);
    cudaFuncSetAttribute(gemm_kernel<false>, cudaFuncAttributeMaxDynamicSharedMemorySize, GEMM_SMEM);

    cudaMemsetAsync(aptr, 0, (size_t)BN * NN, 0);
    sq_kernel<<<BN / 4, 128>>>(x);
    dim3 kg((NN + 31) / 32, BB);
    knn_kernel<<<kg, 256, KNN_SMEM>>>(x);
    agg_kernel<<<BN, 128>>>(x, mp);
    gemm_kernel<true><<<BN / 32, 256, GEMM_SMEM>>>(mp, W1l, x, W1r, b1l, hp);
    agg_kernel<<<BN, 128>>>(hp, mp);
    gemm_kernel<false><<<BN / 32, 256, GEMM_SMEM>>>(mp, W2l, hp, W2r, b2l, out);
}

// round 3
// speedup vs baseline: 1.3099x; 1.3099x over previous
#include <cuda_runtime.h>
#include <cstdint>
#include <cstddef>

#define BB 128
#define NN 400
#define FF 128
#define KNN 5
#define BN (BB * NN)   // 51200

// ---------------- device scratch ----------------
__device__ float g_sq[BN];
__device__ unsigned int g_Abits[(size_t)BN * 16];  // 400-bit adjacency rows (13 words used), 3.3MB
__device__ float g_m[(size_t)BN * FF];
__device__ float g_h[(size_t)BN * FF];

// ---------------- squared norms ----------------
__global__ void sq_kernel(const float* __restrict__ x) {
    int row = blockIdx.x * 4 + (threadIdx.x >> 5);
    int lane = threadIdx.x & 31;
    float4 v = *(const float4*)(x + (size_t)row * FF + lane * 4);
    float s = v.x * v.x + v.y * v.y + v.z * v.z + v.w * v.w;
#pragma unroll
    for (int o = 16; o; o >>= 1) s += __shfl_xor_sync(0xffffffffu, s, o);
    if (lane == 0) g_sq[row] = s;
}

// ---------------- fused distance + top-5 + adjacency scatter ----------------
// 64 i-rows per block, j-tiles of 128, 8x4 thread tile, scores in registers.
#define KNN_SMEM ((128 * 64 + 128 * 128 + 416 + 64 * 5 * 2 + 8 * 5 * 2) * 4)

__global__ void __launch_bounds__(256, 2) knn_kernel(const float* __restrict__ x) {
    extern __shared__ float sm[];
    float* s_xiT = sm;                      // 128k x 64 rows (k-major, swizzled)
    float* s_xjT = s_xiT + 128 * 64;        // 128k x 128 rows
    float* s_sq  = s_xjT + 128 * 128;       // 416
    float* s_bv  = s_sq + 416;              // 64 x 5 running top-5 values
    int*   s_bi  = (int*)(s_bv + 64 * 5);   // 64 x 5 running top-5 indices
    float* s_tv  = (float*)(s_bi + 64 * 5); // 8 x 5 per-warp tile scratch
    int*   s_ti  = (int*)(s_tv + 8 * 5);    // 8 x 5

    const int b  = blockIdx.y;
    const int i0 = blockIdx.x * 64;
    const int t  = threadIdx.x;
    const int tx = t & 31, ty = t >> 5;     // ty = warp id
    const int lane = t & 31;
    const float INF = __int_as_float(0x7f800000);
    const float* xb = x + (size_t)b * NN * FF;

    for (int j = t; j < NN; j += 256) s_sq[j] = g_sq[b * NN + j];
    for (int q = t; q < 64 * KNN; q += 256) { s_bv[q] = INF; s_bi[q] = 0x7fffffff; }

    // load xi tile: 64 rows x 128 k, transpose to k-major, swizzle &15
    for (int idx = t; idx < 512; idx += 256) {
        int ob = idx >> 5, kc = idx & 31;
        float vv[4][4];
#pragma unroll
        for (int r = 0; r < 4; r++) {
            int ir = i0 + ob * 4 + r;
            float4 v = (ir < NN) ? *(const float4*)(xb + (size_t)ir * FF + kc * 4)
                                 : make_float4(0.f, 0.f, 0.f, 0.f);
            vv[r][0] = v.x; vv[r][1] = v.y; vv[r][2] = v.z; vv[r][3] = v.w;
        }
#pragma unroll
        for (int c = 0; c < 4; c++)
            *(float4*)&s_xiT[(kc * 4 + c) * 64 + (((ob ^ kc) & 15) << 2)] =
                make_float4(vv[0][c], vv[1][c], vv[2][c], vv[3][c]);
    }

    for (int j0 = 0; j0 < NN; j0 += 128) {
        __syncthreads();
        // load xj tile: 128 rows x 128 k, k-major swizzled (&31)
        for (int idx = t; idx < 1024; idx += 256) {
            int ob = idx >> 5, kc = idx & 31;
            float vv[4][4];
#pragma unroll
            for (int r = 0; r < 4; r++) {
                int jr = j0 + ob * 4 + r;
                float4 v = (jr < NN) ? *(const float4*)(xb + (size_t)jr * FF + kc * 4)
                                     : make_float4(0.f, 0.f, 0.f, 0.f);
                vv[r][0] = v.x; vv[r][1] = v.y; vv[r][2] = v.z; vv[r][3] = v.w;
            }
#pragma unroll
            for (int c = 0; c < 4; c++)
                *(float4*)&s_xjT[(kc * 4 + c) * 128 + (((ob ^ kc) & 31) << 2)] =
                    make_float4(vv[0][c], vv[1][c], vv[2][c], vv[3][c]);
        }
        __syncthreads();

        float acc[8][4] = {};
#pragma unroll 4
        for (int k = 0; k < 128; k++) {
            int sw = k >> 2;
            float4 a0 = *(const float4*)&s_xiT[k * 64  + ((((2 * ty)     ^ sw) & 15) << 2)];
            float4 a1 = *(const float4*)&s_xiT[k * 64  + ((((2 * ty + 1) ^ sw) & 15) << 2)];
            float4 bj = *(const float4*)&s_xjT[k * 128 + (((tx ^ sw) & 31) << 2)];
            acc[0][0] += a0.x * bj.x; acc[0][1] += a0.x * bj.y; acc[0][2] += a0.x * bj.z; acc[0][3] += a0.x * bj.w;
            acc[1][0] += a0.y * bj.x; acc[1][1] += a0.y * bj.y; acc[1][2] += a0.y * bj.z; acc[1][3] += a0.y * bj.w;
            acc[2][0] += a0.z * bj.x; acc[2][1] += a0.z * bj.y; acc[2][2] += a0.z * bj.z; acc[2][3] += a0.z * bj.w;
            acc[3][0] += a0.w * bj.x; acc[3][1] += a0.w * bj.y; acc[3][2] += a0.w * bj.z; acc[3][3] += a0.w * bj.w;
            acc[4][0] += a1.x * bj.x; acc[4][1] += a1.x * bj.y; acc[4][2] += a1.x * bj.z; acc[4][3] += a1.x * bj.w;
            acc[5][0] += a1.y * bj.x; acc[5][1] += a1.y * bj.y; acc[5][2] += a1.y * bj.z; acc[5][3] += a1.y * bj.w;
            acc[6][0] += a1.z * bj.x; acc[6][1] += a1.z * bj.y; acc[6][2] += a1.z * bj.z; acc[6][3] += a1.z * bj.w;
            acc[7][0] += a1.w * bj.x; acc[7][1] += a1.w * bj.y; acc[7][2] += a1.w * bj.z; acc[7][3] += a1.w * bj.w;
        }

        // scores in registers: row i0+ty*8+rr, col j0+tx*4+c
        float scv[8][4];
#pragma unroll
        for (int rr = 0; rr < 8; rr++)
#pragma unroll
            for (int c = 0; c < 4; c++) {
                int jg = j0 + tx * 4 + c;
                scv[rr][c] = (jg < NN) ? s_sq[jg] - 2.f * acc[rr][c] : INF;
            }

        // per-row top-5 of tile, merged into running top-5
#pragma unroll
        for (int rr = 0; rr < 8; rr++) {
            int irow = i0 + ty * 8 + rr;             // warp-uniform
            if (irow < NN) {
#pragma unroll
                for (int q = 0; q < KNN; q++) {
                    float bv = scv[rr][0]; int bc = 0;
                    if (scv[rr][1] < bv) { bv = scv[rr][1]; bc = 1; }
                    if (scv[rr][2] < bv) { bv = scv[rr][2]; bc = 2; }
                    if (scv[rr][3] < bv) { bv = scv[rr][3]; bc = 3; }
                    int bj = j0 + tx * 4 + bc;
#pragma unroll
                    for (int o = 16; o; o >>= 1) {
                        float ov = __shfl_xor_sync(0xffffffffu, bv, o);
                        int   oj = __shfl_xor_sync(0xffffffffu, bj, o);
                        if (ov < bv || (ov == bv && oj < bj)) { bv = ov; bj = oj; }
                    }
                    if (lane == 0) { s_tv[ty * KNN + q] = bv; s_ti[ty * KNN + q] = bj; }
                    int lc = bj - j0 - tx * 4;
                    if (lc == 0) scv[rr][0] = INF;
                    if (lc == 1) scv[rr][1] = INF;
                    if (lc == 2) scv[rr][2] = INF;
                    if (lc == 3) scv[rr][3] = INF;
                }
                if (lane == 0) {
                    int li = ty * 8 + rr;
                    float rv[KNN]; int ri[KNN];
                    float* av = &s_bv[li * KNN]; int* ai = &s_bi[li * KNN];
                    float* tv = &s_tv[ty * KNN]; int* ti = &s_ti[ty * KNN];
                    int p = 0, q = 0;
#pragma unroll
                    for (int o = 0; o < KNN; o++) {
                        float va = av[p], vt = tv[q];
                        bool takeA = (va < vt) || (va == vt && ai[p] < ti[q]);
                        if (takeA) { rv[o] = va; ri[o] = ai[p]; p++; }
                        else       { rv[o] = vt; ri[o] = ti[q]; q++; }
                    }
#pragma unroll
                    for (int o = 0; o < KNN; o++) { av[o] = rv[o]; ai[o] = ri[o]; }
                }
            }
        }
    }
    __syncthreads();

    // scatter symmetric adjacency bits
    if (t < 64) {
        int il = i0 + t;
        if (il < NN) {
            size_t gi = (size_t)(b * NN + il);
#pragma unroll
            for (int q = 0; q < KNN; q++) {
                int j = s_bi[t * KNN + q];
                atomicOr(&g_Abits[gi * 16 + (j >> 5)], 1u << (j & 31));
                atomicOr(&g_Abits[((size_t)(b * NN + j)) * 16 + (il >> 5)], 1u << (il & 31));
            }
        }
    }
}

// ---------------- mean aggregation: 1 warp per node, bitmask scan ----------------
__global__ void agg_kernel(const float* __restrict__ src, float* __restrict__ dst) {
    __shared__ short s_list[4][NN];
    int w = threadIdx.x >> 5, lane = threadIdx.x & 31;
    int node = blockIdx.x * 4 + w;
    int b = node / NN;
    const unsigned int* Arow = g_Abits + (size_t)node * 16;
    unsigned int m = (lane < 13) ? Arow[lane] : 0u;
    int c = __popc(m);
    int s = c;
#pragma unroll
    for (int o = 1; o < 32; o <<= 1) {
        int v = __shfl_up_sync(0xffffffffu, s, o);
        if (lane >= o) s += v;
    }
    int base = s - c;
    int total = __shfl_sync(0xffffffffu, s, 31);
    unsigned int mm = m; int kpos = 0;
    while (mm) {
        int bit = __ffs(mm) - 1;
        s_list[w][base + kpos] = (short)(lane * 32 + bit);
        kpos++; mm &= mm - 1;
    }
    __syncwarp();
    const float* sb = src + (size_t)b * NN * FF;
    float4 acc = make_float4(0.f, 0.f, 0.f, 0.f);
    for (int e = 0; e < total; e++) {
        float4 v = *(const float4*)(sb + (size_t)s_list[w][e] * FF + lane * 4);
        acc.x += v.x; acc.y += v.y; acc.z += v.z; acc.w += v.w;
    }
    float d = (float)total;
    float4 o = make_float4(acc.x / d, acc.y / d, acc.z / d, acc.w / d);
    *(float4*)(dst + (size_t)node * FF + lane * 4) = o;
}

// ---------------- fused dual-GEMM: out = act( Xa@Wa^T + Xb@Wb^T + bias ) ----------------
// 128x128 block tile, 256 threads, 16x4 thread tile, k-chunks of 64.
#define GEMM_SMEM ((64 * 128 + 64 * 128) * 4)

template <bool RELU>
__global__ void __launch_bounds__(256, 2) gemm_kernel(
        const float* __restrict__ Xa, const float* __restrict__ Wa,
        const float* __restrict__ Xb, const float* __restrict__ Wb,
        const float* __restrict__ bias, float* __restrict__ out) {
    extern __shared__ float sm2[];
    float* s_A = sm2;              // 64k x 128 rows (k-major, swizzled &31)
    float* s_B = sm2 + 64 * 128;   // 64k x 128 cols
    const int r0 = blockIdx.x * 128;
    const int t  = threadIdx.x;
    const int tx = t & 31, ty = t >> 5;    // cols tx*4, rows ty*16..+15
    float acc[16][4] = {};

#pragma unroll
    for (int ch = 0; ch < 4; ch++) {
        const float* X = (ch < 2) ? Xa : Xb;
        const float* W = (ch < 2) ? Wa : Wb;
        const int koff = (ch & 1) * 64;
        if (ch) __syncthreads();
        // load X chunk: 128 rows x 64 k
#pragma unroll
        for (int idx0 = 0; idx0 < 512; idx0 += 256) {
            int idx = idx0 + t;
            int ob = idx >> 4, kc = idx & 15;
            float vv[4][4];
#pragma unroll
            for (int r = 0; r < 4; r++) {
                float4 v = *(const float4*)(X + (size_t)(r0 + ob * 4 + r) * FF + koff + kc * 4);
                vv[r][0] = v.x; vv[r][1] = v.y; vv[r][2] = v.z; vv[r][3] = v.w;
            }
#pragma unroll
            for (int c = 0; c < 4; c++)
                *(float4*)&s_A[(kc * 4 + c) * 128 + (((ob ^ kc) & 31) << 2)] =
                    make_float4(vv[0][c], vv[1][c], vv[2][c], vv[3][c]);
        }
        // load W chunk: 128 out-cols x 64 k
#pragma unroll
        for (int idx0 = 0; idx0 < 512; idx0 += 256) {
            int idx = idx0 + t;
            int ob = idx >> 4, kc = idx & 15;
            float vv[4][4];
#pragma unroll
            for (int r = 0; r < 4; r++) {
                float4 v = *(const float4*)(W + (size_t)(ob * 4 + r) * FF + koff + kc * 4);
                vv[r][0] = v.x; vv[r][1] = v.y; vv[r][2] = v.z; vv[r][3] = v.w;
            }
#pragma unroll
            for (int c = 0; c < 4; c++)
                *(float4*)&s_B[(kc * 4 + c) * 128 + (((ob ^ kc) & 31) << 2)] =
                    make_float4(vv[0][c], vv[1][c], vv[2][c], vv[3][c]);
        }
        __syncthreads();

#pragma unroll 4
        for (int k = 0; k < 64; k++) {
            int sw = k >> 2;
            float4 bv = *(const float4*)&s_B[k * 128 + (((tx ^ sw) & 31) << 2)];
#pragma unroll
            for (int qq = 0; qq < 4; qq++) {
                float4 av = *(const float4*)&s_A[k * 128 + ((((4 * ty + qq) ^ sw) & 31) << 2)];
                acc[qq * 4 + 0][0] += av.x * bv.x; acc[qq * 4 + 0][1] += av.x * bv.y;
                acc[qq * 4 + 0][2] += av.x * bv.z; acc[qq * 4 + 0][3] += av.x * bv.w;
                acc[qq * 4 + 1][0] += av.y * bv.x; acc[qq * 4 + 1][1] += av.y * bv.y;
                acc[qq * 4 + 1][2] += av.y * bv.z; acc[qq * 4 + 1][3] += av.y * bv.w;
                acc[qq * 4 + 2][0] += av.z * bv.x; acc[qq * 4 + 2][1] += av.z * bv.y;
                acc[qq * 4 + 2][2] += av.z * bv.z; acc[qq * 4 + 2][3] += av.z * bv.w;
                acc[qq * 4 + 3][0] += av.w * bv.x; acc[qq * 4 + 3][1] += av.w * bv.y;
                acc[qq * 4 + 3][2] += av.w * bv.z; acc[qq * 4 + 3][3] += av.w * bv.w;
            }
        }
    }

    float4 bv4 = *(const float4*)(bias + tx * 4);
    float bb[4] = {bv4.x, bv4.y, bv4.z, bv4.w};
#pragma unroll
    for (int rr = 0; rr < 16; rr++) {
        int row = r0 + ty * 16 + rr;
        float4 o4;
        float* op = (float*)&o4;
#pragma unroll
        for (int c = 0; c < 4; c++) {
            float v = acc[rr][c] + bb[c];
            if (RELU) v = fmaxf(v, 0.f);
            op[c] = v;
        }
        *(float4*)(out + (size_t)row * FF + tx * 4) = o4;
    }
}

// ---------------- launch ----------------
extern "C" void kernel_launch(void* const* d_in, const int* in_sizes, int n_in,
                              void* d_out, int out_size) {
    const float* x   = (const float*)d_in[0];
    const float* W1l = (const float*)d_in[1];
    const float* b1l = (const float*)d_in[2];
    const float* W1r = (const float*)d_in[3];
    const float* W2l = (const float*)d_in[4];
    const float* b2l = (const float*)d_in[5];
    const float* W2r = (const float*)d_in[6];
    float* out = (float*)d_out;

    void* aptr = nullptr;
    cudaGetSymbolAddress(&aptr, g_Abits);
    float* mp = nullptr; cudaGetSymbolAddress((void**)&mp, g_m);
    float* hp = nullptr; cudaGetSymbolAddress((void**)&hp, g_h);

    cudaFuncSetAttribute(knn_kernel, cudaFuncAttributeMaxDynamicSharedMemorySize, KNN_SMEM);
    cudaFuncSetAttribute(gemm_kernel<true>,  cudaFuncAttributeMaxDynamicSharedMemorySize, GEMM_SMEM);
    cudaFuncSetAttribute(gemm_kernel<false>, cudaFuncAttributeMaxDynamicSharedMemorySize, GEMM_SMEM);

    cudaMemsetAsync(aptr, 0, (size_t)BN * 16 * sizeof(unsigned int), 0);
    sq_kernel<<<BN / 4, 128>>>(x);
    dim3 kg(7, BB);
    knn_kernel<<<kg, 256, KNN_SMEM>>>(x);
    agg_kernel<<<BN / 4, 128>>>(x, mp);
    gemm_kernel<true><<<BN / 128, 256, GEMM_SMEM>>>(mp, W1l, x, W1r, b1l, hp);
    agg_kernel<<<BN / 4, 128>>>(hp, mp);
    gemm_kernel<false><<<BN / 128, 256, GEMM_SMEM>>>(mp, W2l, hp, W2r, b2l, out);
}